// round 1
// baseline (speedup 1.0000x reference)
#include <cuda_runtime.h>
#include <cstdint>

// ---------------------------------------------------------------------------
// S4D kernel materialization:
//   K[d,l] = 2*Re( sum_n Cc[d,n] * exp(dtA[d,n] * l) ),  D=512, N=32, L=8192
//
// Strategy:
//   x_n(l) = Re(u_n * r_n^l) satisfies the stable 2-term real recurrence
//       x_{k+1} = 2Re(r^T) x_k - |r^T|^2 x_{k-1}
//   when sampled with stride T. Each thread owns one (d, t) and produces
//   l = t, t+T, t+2T, ... via the recurrence (no transcendentals in loop).
//   States are packed 2-wide and advanced with fma.rn.f32x2 (Blackwell).
// ---------------------------------------------------------------------------

#define D_MODEL 512
#define NSTATE  32
#define SEQ     8192
#define TSTRIDE 111                    // 512*111 = 56832 = 444 blocks * 128
#define MAIN_BLOCKS 444
#define MAIN_THREADS 128

typedef unsigned long long u64;

// Precomputed per (d,n): dtA, discretized 2*Cc, r^T = exp(dtA*T)
__device__ float2 g_dtA[D_MODEL * NSTATE];
__device__ float2 g_Cc [D_MODEL * NSTATE];
__device__ float2 g_rT [D_MODEL * NSTATE];

// ---- packed f32x2 helpers --------------------------------------------------
__device__ __forceinline__ u64 pack2(float lo, float hi) {
    u64 r; asm("mov.b64 %0, {%1, %2};" : "=l"(r) : "f"(lo), "f"(hi)); return r;
}
__device__ __forceinline__ void unpack2(u64 v, float& lo, float& hi) {
    asm("mov.b64 {%0, %1}, %2;" : "=f"(lo), "=f"(hi) : "l"(v));
}
__device__ __forceinline__ u64 add2(u64 a, u64 b) {
    u64 d; asm("add.rn.f32x2 %0, %1, %2;" : "=l"(d) : "l"(a), "l"(b)); return d;
}
__device__ __forceinline__ u64 mul2(u64 a, u64 b) {
    u64 d; asm("mul.rn.f32x2 %0, %1, %2;" : "=l"(d) : "l"(a), "l"(b)); return d;
}
__device__ __forceinline__ u64 fma2(u64 a, u64 b, u64 c) {
    u64 d; asm("fma.rn.f32x2 %0, %1, %2, %3;" : "=l"(d) : "l"(a), "l"(b), "l"(c)); return d;
}

// ---------------------------------------------------------------------------
// Kernel 1: discretization precompute, one thread per (d, n). Precise math.
// ---------------------------------------------------------------------------
__global__ void s4d_precompute_kernel(const float* __restrict__ log_dt,
                                      const float* __restrict__ log_A_real,
                                      const float* __restrict__ A_imag,
                                      const float2* __restrict__ C)
{
    int i = blockIdx.x * blockDim.x + threadIdx.x;
    if (i >= D_MODEL * NSTATE) return;
    int d = i >> 5;  // / NSTATE

    float dt   = expf(log_dt[d]);
    float Ar   = -expf(log_A_real[i]);
    float Ai   = A_imag[i];
    float dtAr = Ar * dt;
    float dtAi = Ai * dt;

    // E = exp(dtA) - 1
    float er = expf(dtAr);
    float s, c;
    sincosf(dtAi, &s, &c);
    float Er = er * c - 1.0f;
    float Ei = er * s;

    // q = E / (A + 1e-8)   (1e-8 added to real part, matching reference)
    float ar8 = Ar + 1e-8f;
    float inv = 1.0f / (ar8 * ar8 + Ai * Ai);
    float qr = (Er * ar8 + Ei * Ai) * inv;
    float qi = (Ei * ar8 - Er * Ai) * inv;

    // Cc = C * q, with the final 2x output scale folded in
    float2 Cv  = C[i];
    float Ccr = 2.0f * (Cv.x * qr - Cv.y * qi);
    float Cci = 2.0f * (Cv.x * qi + Cv.y * qr);

    // r^T = exp(dtA * T)
    float eT = expf(dtAr * (float)TSTRIDE);
    float sT, cT;
    sincosf(dtAi * (float)TSTRIDE, &sT, &cT);

    g_dtA[i] = make_float2(dtAr, dtAi);
    g_Cc[i]  = make_float2(Ccr, Cci);
    g_rT[i]  = make_float2(eT * cT, eT * sT);
}

// Per-state init for the main kernel: exact x(t), x(t+T) and recurrence coefs.
// Fast intrinsics: |dtAr*t| <= ~10, |dtAi*t| <= ~35 -> error ~1e-5, fine.
__device__ __forceinline__ void init_state(int idx, float ft,
                                           float& xa, float& xb,
                                           float& a2, float& mn)
{
    float2 da = g_dtA[idx];
    float2 cc = g_Cc[idx];
    float2 rt = g_rT[idx];
    float e = __expf(da.x * ft);
    float s, c;
    __sincosf(da.y * ft, &s, &c);
    float wr = e * c, wi = e * s;                 // exp(dtA * t)
    float ur = cc.x * wr - cc.y * wi;             // u = Cc * exp(dtA*t)
    float ui = cc.x * wi + cc.y * wr;
    xa = ur;                                      // x(t)   = Re(u)
    xb = ur * rt.x - ui * rt.y;                   // x(t+T) = Re(u * r^T)
    a2 = rt.x + rt.x;                             // 2*Re(r^T)
    mn = -(rt.x * rt.x + rt.y * rt.y);            // -|r^T|^2
}

// ---------------------------------------------------------------------------
// Kernel 2: main recurrence. One thread per (d, t), t in [0, TSTRIDE).
// Grid is exactly one wave: 444 blocks * 128 thr = 148 SMs * 3 CTAs.
// ---------------------------------------------------------------------------
__global__ void __launch_bounds__(MAIN_THREADS, 3)
s4d_main_kernel(float* __restrict__ out)
{
    unsigned g = blockIdx.x * MAIN_THREADS + threadIdx.x;
    unsigned d = g / TSTRIDE;
    unsigned t = g - d * TSTRIDE;
    float ft = (float)t;
    int base = (int)(d * NSTATE);

    u64 XA[16], XB[16], A2[16], MN[16];

#pragma unroll
    for (int j = 0; j < 16; j++) {
        float xa0, xb0, a20, mn0, xa1, xb1, a21, mn1;
        init_state(base + 2 * j,     ft, xa0, xb0, a20, mn0);
        init_state(base + 2 * j + 1, ft, xa1, xb1, a21, mn1);
        XA[j] = pack2(xa0, xa1);
        XB[j] = pack2(xb0, xb1);
        A2[j] = pack2(a20, a21);
        MN[j] = pack2(mn0, mn1);
    }

    float* op = out + (size_t)d * SEQ;
    int l = (int)t;

    // Ping-pong unroll-by-2: no register moves in the rotate.
    for (;;) {
        // emit x_k (held in XA)
        u64 acc = XA[0];
#pragma unroll
        for (int j = 1; j < 16; j++) acc = add2(acc, XA[j]);
        float lo, hi;
        unpack2(acc, lo, hi);
        op[l] = lo + hi;
        l += TSTRIDE;
        if (l >= SEQ) break;

        // XA <- x_{k+2} = a2*XB + mn*XA
#pragma unroll
        for (int j = 0; j < 16; j++) XA[j] = fma2(A2[j], XB[j], mul2(MN[j], XA[j]));

        // emit x_{k+1} (held in XB)
        acc = XB[0];
#pragma unroll
        for (int j = 1; j < 16; j++) acc = add2(acc, XB[j]);
        unpack2(acc, lo, hi);
        op[l] = lo + hi;
        l += TSTRIDE;
        if (l >= SEQ) break;

        // XB <- x_{k+3} = a2*XA + mn*XB
#pragma unroll
        for (int j = 0; j < 16; j++) XB[j] = fma2(A2[j], XA[j], mul2(MN[j], XB[j]));
    }
}

// ---------------------------------------------------------------------------
extern "C" void kernel_launch(void* const* d_in, const int* in_sizes, int n_in,
                              void* d_out, int out_size)
{
    const float*  log_dt     = (const float*)d_in[0];
    const float*  log_A_real = (const float*)d_in[1];
    const float*  A_imag     = (const float*)d_in[2];
    const float2* C          = (const float2*)d_in[3];
    float* out = (float*)d_out;

    s4d_precompute_kernel<<<(D_MODEL * NSTATE + 255) / 256, 256>>>(
        log_dt, log_A_real, A_imag, C);
    s4d_main_kernel<<<MAIN_BLOCKS, MAIN_THREADS>>>(out);
}